// round 14
// baseline (speedup 1.0000x reference)
#include <cuda_runtime.h>
#include <math.h>

#define NB 148
#define THREADS 512
#define BATCH 64
#define NPG 9
#define NTOT (BATCH*NPG)   // 576
#define H 128
#define K1 1801
#define O1 900
#define O2 100
#define ASL 243
#define NT1 15             // 15 n-tiles x 64 outs
#define KS1 9
#define KC1 201            // 9*201 = 1809 >= 1801
#define NG2 20             // gemm2 crew blocks; 900 = 20*45
#define KC2 45

// scratch (no allocation allowed)
__device__ float g_s1_part[KS1 * BATCH * O1];
__device__ float g_s2_part[NG2 * BATCH * O2];
__device__ float g_Ai[NTOT * H];
__device__ float g_Bj[NTOT * H];
__device__ unsigned g_abflag[BATCH];
__device__ unsigned g_s2cnt;
__device__ unsigned g_count = 0;
__device__ unsigned g_gen = 0;

__device__ __forceinline__ void grid_barrier() {
    __syncthreads();
    __threadfence();
    if (threadIdx.x == 0) {
        unsigned gen = *(volatile unsigned*)&g_gen;
        if (atomicAdd(&g_count, 1u) == NB - 1) {
            g_count = 0;
            __threadfence();
            atomicAdd(&g_gen, 1u);
        } else {
            while (*(volatile unsigned*)&g_gen == gen) __nanosleep(32);
        }
    }
    __syncthreads();
}

__global__ __launch_bounds__(THREADS, 1)
void fused_kernel(const float* __restrict__ nf, const float* __restrict__ spec,
                  const float* __restrict__ mask, const int* __restrict__ imask,
                  const float* __restrict__ W1, const float* __restrict__ b1,
                  const float* __restrict__ W2, const float* __restrict__ b2,
                  const float* __restrict__ Wv1, const float* __restrict__ bv1,
                  const float* __restrict__ Wv2, const float* __restrict__ bv2,
                  const float* __restrict__ Wa2, const float* __restrict__ ba2,
                  const float* __restrict__ Wf, const float* __restrict__ bf,
                  float* __restrict__ out) {
    __shared__ __align__(16) float buf[12288];   // 48KB, reused per phase
    const int t = threadIdx.x;
    const int bid = blockIdx.x;

    // reset flags (ordered before use by grid_barrier's fence)
    if (bid < BATCH && t == 0) g_abflag[bid] = 0;
    if (bid == 147 && t == 0) g_s2cnt = 0;

    // ===== Phase 1: gemm1 (135 blocks; single-sync double-buffer, sw-pipelined) =====
    if (bid < NT1 * KS1) {
        const int nt = bid / KS1, ks = bid % KS1;
        const int og = t & 31;
        const int bg = t >> 5;
        const int o0 = nt * 64 + og * 2;
        const int b0 = bg * 4;
        const int kbeg = ks * KC1;
        const int kend = min(kbeg + KC1, K1);
        const int nch = (kend - kbeg + 31) >> 5;
        // double buffers: sp[p]=buf+p*4352, wt[p]=sp+2176

        const int kk_s = t & 31;
        const int bb_s = t >> 5;
        const int kk_w = t >> 6;
        const int oo_w = t & 63;
        const int ow_g = nt * 64 + oo_w;
        const bool wok = (ow_g < O1);

        float rsv[4], rwv[4];
        {
            const int k0 = kbeg;
            const int klen = kend - k0;
#pragma unroll
            for (int j = 0; j < 4; j++)
                rsv[j] = (kk_s < klen) ? spec[(bb_s + 16 * j) * K1 + k0 + kk_s] : 0.f;
#pragma unroll
            for (int j = 0; j < 4; j++) {
                int kk = kk_w + 8 * j;
                rwv[j] = (kk < klen && wok) ? W1[(k0 + kk) * O1 + ow_g] : 0.f;
            }
        }
        float a00 = 0.f, a01 = 0.f, a10 = 0.f, a11 = 0.f;
        float a20 = 0.f, a21 = 0.f, a30 = 0.f, a31 = 0.f;

        for (int c = 0; c < nch; c++) {
            float* sp = buf + (c & 1) * 4352;
            float* wt = sp + 2176;
#pragma unroll
            for (int j = 0; j < 4; j++)
                sp[kk_s * 68 + bb_s + 16 * j] = rsv[j];
#pragma unroll
            for (int j = 0; j < 4; j++)
                wt[(kk_w + 8 * j) * 68 + oo_w] = rwv[j];
            __syncthreads();
            if (c + 1 < nch) {
                const int k0 = kbeg + (c + 1) * 32;
                const int klen = kend - k0;
#pragma unroll
                for (int j = 0; j < 4; j++)
                    rsv[j] = (kk_s < klen) ? spec[(bb_s + 16 * j) * K1 + k0 + kk_s] : 0.f;
#pragma unroll
                for (int j = 0; j < 4; j++) {
                    int kk = kk_w + 8 * j;
                    rwv[j] = (kk < klen && wok) ? W1[(k0 + kk) * O1 + ow_g] : 0.f;
                }
            }
            // software-pipelined smem loads
            float4 s4 = *(const float4*)(sp + b0);
            float2 w2 = *(const float2*)(wt + og * 2);
#pragma unroll
            for (int kk = 0; kk < 32; kk++) {
                float4 s4c = s4;
                float2 w2c = w2;
                if (kk < 31) {
                    s4 = *(const float4*)(sp + (kk + 1) * 68 + b0);
                    w2 = *(const float2*)(wt + (kk + 1) * 68 + og * 2);
                }
                a00 += s4c.x * w2c.x; a01 += s4c.x * w2c.y;
                a10 += s4c.y * w2c.x; a11 += s4c.y * w2c.y;
                a20 += s4c.z * w2c.x; a21 += s4c.z * w2c.y;
                a30 += s4c.w * w2c.x; a31 += s4c.w * w2c.y;
            }
        }
        float* dst = g_s1_part + ks * (BATCH * O1);
        if (o0 + 1 < O1) {
            dst[(b0 + 0) * O1 + o0] = a00; dst[(b0 + 0) * O1 + o0 + 1] = a01;
            dst[(b0 + 1) * O1 + o0] = a10; dst[(b0 + 1) * O1 + o0 + 1] = a11;
            dst[(b0 + 2) * O1 + o0] = a20; dst[(b0 + 2) * O1 + o0 + 1] = a21;
            dst[(b0 + 3) * O1 + o0] = a30; dst[(b0 + 3) * O1 + o0 + 1] = a31;
        } else if (o0 < O1) {
            dst[(b0 + 0) * O1 + o0] = a00;
            dst[(b0 + 1) * O1 + o0] = a10;
            dst[(b0 + 2) * O1 + o0] = a20;
            dst[(b0 + 3) * O1 + o0] = a30;
        }
    }

    grid_barrier();

    // ===== Phase 2 =====
    if (bid >= 128) {
        // ---- gemm2 crew (blocks 128-147): k-chunk of 45, all 64 graphs ----
        const int cb = bid - 128;          // 0..19
        const int kb = cb * KC2;
        float* s1c = buf;                  // [45][68] k-major
        float* w2s = buf + 3060;           // [45][100]
        for (int idx = t; idx < KC2 * O2; idx += THREADS)
            w2s[idx] = W2[(size_t)kb * O2 + idx];
        for (int idx = t; idx < BATCH * KC2; idx += THREADS) {
            int b = idx / KC2, kk = idx - b * KC2;
            float v = b1[kb + kk];
#pragma unroll
            for (int c = 0; c < KS1; c++)
                v += g_s1_part[c * (BATCH * O1) + b * O1 + kb + kk];
            s1c[kk * 68 + b] = fmaxf(v, 0.f);
        }
        __syncthreads();
        const int o = t & 127;             // out (0..99 valid)
        const int bq = t >> 7;             // 0..3 -> batches bq*16..+15
        if (o < O2) {
            float acc[16];
#pragma unroll
            for (int n = 0; n < 16; n++) acc[n] = 0.f;
#pragma unroll
            for (int kk = 0; kk < KC2; kk++) {
                float wv = w2s[kk * O2 + o];
                const float* sc = s1c + kk * 68 + bq * 16;
                float4 s0 = *(const float4*)sc;
                float4 s1 = *(const float4*)(sc + 4);
                float4 s2 = *(const float4*)(sc + 8);
                float4 s3 = *(const float4*)(sc + 12);
                acc[0] += s0.x * wv; acc[1] += s0.y * wv;
                acc[2] += s0.z * wv; acc[3] += s0.w * wv;
                acc[4] += s1.x * wv; acc[5] += s1.y * wv;
                acc[6] += s1.z * wv; acc[7] += s1.w * wv;
                acc[8] += s2.x * wv; acc[9] += s2.y * wv;
                acc[10] += s2.z * wv; acc[11] += s2.w * wv;
                acc[12] += s3.x * wv; acc[13] += s3.y * wv;
                acc[14] += s3.z * wv; acc[15] += s3.w * wv;
            }
            float* dst = g_s2_part + cb * (BATCH * O2);
#pragma unroll
            for (int n = 0; n < 16; n++)
                dst[(bq * 16 + n) * O2 + o] = acc[n];
        }
        __threadfence();
        __syncthreads();
        if (t == 0) atomicAdd(&g_s2cnt, 1u);
    } else if (bid >= 64) {
        // ---- ab writer for graph b = bid-64 ----
        const int b = bid - 64;
        float* nfs_t = buf;           // [128][12] transposed relu(nf)
        float* Pq    = buf + 1536;    // 2304 partials for q=1
        for (int idx = t; idx < NPG * H; idx += THREADS) {
            int i = idx >> 7, k = idx & 127;
            nfs_t[k * 12 + i] = fmaxf(nf[(b * NPG + i) * H + k], 0.f);
        }
        __syncthreads();
        const int c = t & 255, q = t >> 8;
        const int kb = q * 64;
        const float* wbase = Wa2 + ((c < 128) ? c : (H * H + (c - 128)));
        float accp[9];
#pragma unroll
        for (int i = 0; i < 9; i++) accp[i] = 0.f;
#pragma unroll 4
        for (int k = 0; k < 64; k++) {
            const int kg = kb + k;
            float wv = wbase[(size_t)kg * H];
            const float* nr = nfs_t + kg * 12;
            float4 n0 = *(const float4*)nr;
            float4 n1 = *(const float4*)(nr + 4);
            float n8 = nr[8];
            accp[0] += n0.x * wv; accp[1] += n0.y * wv;
            accp[2] += n0.z * wv; accp[3] += n0.w * wv;
            accp[4] += n1.x * wv; accp[5] += n1.y * wv;
            accp[6] += n1.z * wv; accp[7] += n1.w * wv;
            accp[8] += n8 * wv;
        }
        if (q == 1) {
#pragma unroll
            for (int i = 0; i < 9; i++) Pq[c * 9 + i] = accp[i];
        }
        __syncthreads();
        if (q == 0) {
            float* g = (c < 128) ? g_Ai : g_Bj;
            const int cc = (c < 128) ? c : (c - 128);
#pragma unroll
            for (int i = 0; i < 9; i++)
                g[(b * NPG + i) * H + cc] = accp[i] + Pq[c * 9 + i];
        }
        __threadfence();
        __syncthreads();
        if (t == 0) atomicExch(&g_abflag[b], 1u);
    } else {
        // ---- per-graph reader ----
        const int b = bid;
        const int lane = t & 31, w = t >> 5;
        float* As    = buf + 2912;     // 9*132
        float* Bs    = buf + 4100;     // 9*132
        float* Wft   = buf + 5288;     // 384 bond-major
        float* x     = buf + 5672;     // 232 used (pad 256)
        float* ss    = buf + 5928;     // 100 (pad 128)
        float* Dc    = buf + 6056;     // 128
        float* hred  = buf + 6184;     // 2 (warp sums)
        float* fp2   = buf + 6248;     // 486 (pad 512)
        float* fp    = buf + 6760;     // 243 (pad 256)
        float* Dpart = buf + 7016;     // 512
        float* Vpart = buf + 7528;     // 512
        float* red   = buf + 8040;     // 16
        float* rs2   = buf + 8056;     // 2

        // --- stage A: Wft; readout x[0:128]; x pad zeros
        for (int idx = t; idx < H * 3; idx += THREADS)
            Wft[(idx % 3) * H + idx / 3] = Wf[idx];
        if (t < H) {
            float sum = 0.f;
#pragma unroll
            for (int i = 0; i < NPG; i++) sum += nf[(b * NPG + i) * H + t];
            x[t] = sum;
        }
        if (t >= 228 && t < 232) x[t] = 0.f;
        __syncthreads();

        // --- wait for gemm2 crew, then ss reduce
        if (t == 0) {
            while (atomicAdd(&g_s2cnt, 0u) < NG2) __nanosleep(32);
            __threadfence();
        }
        __syncthreads();
        if (t < O2) {
            float a = b2[t];
#pragma unroll
            for (int q = 0; q < NG2; q++)
                a += g_s2_part[q * (BATCH * O2) + b * O2 + t];
            ss[t] = fmaxf(a, 0.f);
        }
        __syncthreads();

        // --- wait for ab writer (block b+64)
        if (t == 0) {
            while (atomicAdd(&g_abflag[b], 0u) == 0) __nanosleep(32);
            __threadfence();
        }
        __syncthreads();

        // --- stage D: x tail; As/Bs from global; D partials
        if (t < O2) x[H + t] = ss[t];
        for (int idx = t; idx < NPG * 256; idx += THREADS) {
            int i = idx >> 8, c = idx & 255;
            if (c < 128) As[i * 132 + c] = g_Ai[(b * NPG + i) * H + c];
            else         Bs[i * 132 + c - 128] = g_Bj[(b * NPG + i) * H + c - 128];
        }
        {
            const int o = t & 127, q = t >> 7;
            const int kb = q * 25;
            float d = 0.f;
#pragma unroll
            for (int kk = 0; kk < 25; kk++)
                d += ss[kb + kk] * Wa2[(size_t)(2 * H + kb + kk) * H + o];
            Dpart[q * H + o] = d;
        }
        __syncthreads();

        // --- stage E: V partials (uniform 29, fully unrolled); Dc
        {
            const int o = t & 63, q = t >> 6;
            const int kb = q * 29;
            float v = 0.f;
#pragma unroll
            for (int kk = 0; kk < 29; kk++)
                v += x[kb + kk] * Wv1[(size_t)(kb + kk) * 64 + o];
            Vpart[q * 64 + o] = v;
        }
        if (t < H)
            Dc[t] = ba2[t] + Dpart[t] + Dpart[H + t] + Dpart[2 * H + t] + Dpart[3 * H + t];
        __syncthreads();

        // --- stage F: value hidden (shuffle-reduced); pair logits
        if (t < 64) {
            float a = bv1[t];
#pragma unroll
            for (int q = 0; q < 8; q++) a += Vpart[q * 64 + t];
            float hv = fmaxf(a, 0.f) * Wv2[t];
#pragma unroll
            for (int off = 16; off; off >>= 1)
                hv += __shfl_xor_sync(0xffffffffu, hv, off);
            if ((t & 31) == 0) hred[t >> 5] = hv;
        }
        if (t < 486) {
            const int half = (t >= ASL) ? 1 : 0;
            const int pi = t - ASL * half;
            const int pair = pi / 3, bond = pi - pair * 3;
            const int i = pair / NPG, j = pair - i * NPG;
            const float4* Ap = (const float4*)(As + i * 132) + half * 16;
            const float4* Bp = (const float4*)(Bs + j * 132) + half * 16;
            const float4* Dp = (const float4*)Dc + half * 16;
            const float4* Wp = (const float4*)(Wft + bond * H) + half * 16;
            float a = 0.f;
#pragma unroll
            for (int q = 0; q < 16; q++) {
                float4 av = Ap[q], bv = Bp[q], dv = Dp[q], wv = Wp[q];
                a += fmaxf(av.x + bv.x + dv.x, 0.f) * wv.x
                   + fmaxf(av.y + bv.y + dv.y, 0.f) * wv.y
                   + fmaxf(av.z + bv.z + dv.z, 0.f) * wv.z
                   + fmaxf(av.w + bv.w + dv.w, 0.f) * wv.w;
            }
            fp2[t] = a;
        }
        __syncthreads();
        if (t < ASL) fp[t] = fp2[t] + fp2[ASL + t] + bf[t % 3];
        __syncthreads();

        // --- gather + softmax + value out
        float g = -INFINITY;
        if (t < ASL) g = fp[imask[b * ASL + t]] + mask[b * ASL + t];
        float v = g;
#pragma unroll
        for (int off = 16; off; off >>= 1) v = fmaxf(v, __shfl_xor_sync(0xffffffffu, v, off));
        if (lane == 0) red[w] = v;
        __syncthreads();
        if (t == 0) {
            float m = red[0];
#pragma unroll
            for (int i = 1; i < 16; i++) m = fmaxf(m, red[i]);
            rs2[0] = m;
        }
        __syncthreads();
        float e = (t < ASL) ? __expf(g - rs2[0]) : 0.f;
        v = e;
#pragma unroll
        for (int off = 16; off; off >>= 1) v += __shfl_xor_sync(0xffffffffu, v, off);
        if (lane == 0) red[w] = v;
        __syncthreads();
        if (t == 0) {
            float s = 0.f;
#pragma unroll
            for (int i = 0; i < 16; i++) s += red[i];
            rs2[1] = s;
            out[BATCH * ASL + b] = bv2[0] + hred[0] + hred[1];
        }
        __syncthreads();
        if (t < ASL) out[b * ASL + t] = e / rs2[1];
    }
}

extern "C" void kernel_launch(void* const* d_in, const int* in_sizes, int n_in,
                              void* d_out, int out_size) {
    const float* nf   = (const float*)d_in[0];
    const float* spec = (const float*)d_in[1];
    const float* mask = (const float*)d_in[3];
    const int*   imask= (const int*)  d_in[4];
    const float* W1   = (const float*)d_in[5];
    const float* b1   = (const float*)d_in[6];
    const float* W2   = (const float*)d_in[7];
    const float* b2   = (const float*)d_in[8];
    const float* Wv1  = (const float*)d_in[9];
    const float* bv1  = (const float*)d_in[10];
    const float* Wv2  = (const float*)d_in[11];
    const float* bv2  = (const float*)d_in[12];
    const float* Wa2  = (const float*)d_in[13];
    const float* ba2  = (const float*)d_in[14];
    const float* Wf   = (const float*)d_in[15];
    const float* bf   = (const float*)d_in[16];
    float* out = (float*)d_out;

    fused_kernel<<<NB, THREADS>>>(nf, spec, mask, imask, W1, b1, W2, b2,
                                  Wv1, bv1, Wv2, bv2, Wa2, ba2, Wf, bf, out);
}

// round 15
// speedup vs baseline: 1.1476x; 1.1476x over previous
#include <cuda_runtime.h>
#include <math.h>

#define NB 148
#define THREADS 512
#define BATCH 64
#define NPG 9
#define NTOT (BATCH*NPG)   // 576
#define H 128
#define K1 1801
#define O1 900
#define O2 100
#define ASL 243
#define NT1 15             // 15 n-tiles x 64 outs
#define KS1 9
#define KC1 201            // 9*201 = 1809 >= 1801

// scratch (no allocation allowed)
__device__ float g_s1_part[KS1 * BATCH * O1];
__device__ float g_Ai[NTOT * H];
__device__ float g_Bj[NTOT * H];
__device__ unsigned g_abflag[BATCH];
__device__ unsigned g_count = 0;
__device__ unsigned g_gen = 0;

__device__ __forceinline__ void grid_barrier() {
    __syncthreads();
    __threadfence();
    if (threadIdx.x == 0) {
        unsigned gen = *(volatile unsigned*)&g_gen;
        if (atomicAdd(&g_count, 1u) == NB - 1) {
            g_count = 0;
            __threadfence();
            atomicAdd(&g_gen, 1u);
        } else {
            while (*(volatile unsigned*)&g_gen == gen) __nanosleep(32);
        }
    }
    __syncthreads();
}

__global__ __launch_bounds__(THREADS, 1)
void fused_kernel(const float* __restrict__ nf, const float* __restrict__ spec,
                  const float* __restrict__ mask, const int* __restrict__ imask,
                  const float* __restrict__ W1, const float* __restrict__ b1,
                  const float* __restrict__ W2, const float* __restrict__ b2,
                  const float* __restrict__ Wv1, const float* __restrict__ bv1,
                  const float* __restrict__ Wv2, const float* __restrict__ bv2,
                  const float* __restrict__ Wa2, const float* __restrict__ ba2,
                  const float* __restrict__ Wf, const float* __restrict__ bf,
                  float* __restrict__ out) {
    __shared__ __align__(16) float buf[12288];   // 48KB, reused per phase
    const int t = threadIdx.x;
    const int bid = blockIdx.x;

    // reset per-graph ab flags (ordered before release by grid_barrier's fence)
    if (bid < BATCH && t == 0) g_abflag[bid] = 0;

    // ===== Phase 1: gemm1 (135 blocks; single-sync double-buffer, sw-pipelined) =====
    if (bid < NT1 * KS1) {
        const int nt = bid / KS1, ks = bid % KS1;
        const int og = t & 31;
        const int bg = t >> 5;
        const int o0 = nt * 64 + og * 2;
        const int b0 = bg * 4;
        const int kbeg = ks * KC1;
        const int kend = min(kbeg + KC1, K1);
        const int nch = (kend - kbeg + 31) >> 5;
        // double buffers: sp[p]=buf+p*4352, wt[p]=sp+2176

        const int kk_s = t & 31;
        const int bb_s = t >> 5;
        const int kk_w = t >> 6;
        const int oo_w = t & 63;
        const int ow_g = nt * 64 + oo_w;
        const bool wok = (ow_g < O1);

        float rsv[4], rwv[4];
        {
            const int k0 = kbeg;
            const int klen = kend - k0;
#pragma unroll
            for (int j = 0; j < 4; j++)
                rsv[j] = (kk_s < klen) ? spec[(bb_s + 16 * j) * K1 + k0 + kk_s] : 0.f;
#pragma unroll
            for (int j = 0; j < 4; j++) {
                int kk = kk_w + 8 * j;
                rwv[j] = (kk < klen && wok) ? W1[(k0 + kk) * O1 + ow_g] : 0.f;
            }
        }
        float a00 = 0.f, a01 = 0.f, a10 = 0.f, a11 = 0.f;
        float a20 = 0.f, a21 = 0.f, a30 = 0.f, a31 = 0.f;

        for (int c = 0; c < nch; c++) {
            float* sp = buf + (c & 1) * 4352;
            float* wt = sp + 2176;
#pragma unroll
            for (int j = 0; j < 4; j++)
                sp[kk_s * 68 + bb_s + 16 * j] = rsv[j];
#pragma unroll
            for (int j = 0; j < 4; j++)
                wt[(kk_w + 8 * j) * 68 + oo_w] = rwv[j];
            __syncthreads();
            if (c + 1 < nch) {
                const int k0 = kbeg + (c + 1) * 32;
                const int klen = kend - k0;
#pragma unroll
                for (int j = 0; j < 4; j++)
                    rsv[j] = (kk_s < klen) ? spec[(bb_s + 16 * j) * K1 + k0 + kk_s] : 0.f;
#pragma unroll
                for (int j = 0; j < 4; j++) {
                    int kk = kk_w + 8 * j;
                    rwv[j] = (kk < klen && wok) ? W1[(k0 + kk) * O1 + ow_g] : 0.f;
                }
            }
            // software-pipelined smem loads
            float4 s4 = *(const float4*)(sp + b0);
            float2 w2 = *(const float2*)(wt + og * 2);
#pragma unroll
            for (int kk = 0; kk < 32; kk++) {
                float4 s4c = s4;
                float2 w2c = w2;
                if (kk < 31) {
                    s4 = *(const float4*)(sp + (kk + 1) * 68 + b0);
                    w2 = *(const float2*)(wt + (kk + 1) * 68 + og * 2);
                }
                a00 += s4c.x * w2c.x; a01 += s4c.x * w2c.y;
                a10 += s4c.y * w2c.x; a11 += s4c.y * w2c.y;
                a20 += s4c.z * w2c.x; a21 += s4c.z * w2c.y;
                a30 += s4c.w * w2c.x; a31 += s4c.w * w2c.y;
            }
        }
        float* dst = g_s1_part + ks * (BATCH * O1);
        if (o0 + 1 < O1) {
            dst[(b0 + 0) * O1 + o0] = a00; dst[(b0 + 0) * O1 + o0 + 1] = a01;
            dst[(b0 + 1) * O1 + o0] = a10; dst[(b0 + 1) * O1 + o0 + 1] = a11;
            dst[(b0 + 2) * O1 + o0] = a20; dst[(b0 + 2) * O1 + o0 + 1] = a21;
            dst[(b0 + 3) * O1 + o0] = a30; dst[(b0 + 3) * O1 + o0 + 1] = a31;
        } else if (o0 < O1) {
            dst[(b0 + 0) * O1 + o0] = a00;
            dst[(b0 + 1) * O1 + o0] = a10;
            dst[(b0 + 2) * O1 + o0] = a20;
            dst[(b0 + 3) * O1 + o0] = a30;
        }
    }

    grid_barrier();

    // ===== Phase 2 =====
    if (bid >= 64 && bid < 128) {
        // ---- ab writer for graph b = bid-64 ----
        const int b = bid - 64;
        float* nfs_t = buf;           // [128][12] transposed relu(nf)
        float* Pq    = buf + 1536;    // 2304 partials for q=1
        for (int idx = t; idx < NPG * H; idx += THREADS) {
            int i = idx >> 7, k = idx & 127;
            nfs_t[k * 12 + i] = fmaxf(nf[(b * NPG + i) * H + k], 0.f);
        }
        __syncthreads();
        const int c = t & 255, q = t >> 8;
        const int kb = q * 64;
        const float* wbase = Wa2 + ((c < 128) ? c : (H * H + (c - 128)));
        float accp[9];
#pragma unroll
        for (int i = 0; i < 9; i++) accp[i] = 0.f;
#pragma unroll 4
        for (int k = 0; k < 64; k++) {
            const int kg = kb + k;
            float wv = wbase[(size_t)kg * H];
            const float* nr = nfs_t + kg * 12;
            float4 n0 = *(const float4*)nr;
            float4 n1 = *(const float4*)(nr + 4);
            float n8 = nr[8];
            accp[0] += n0.x * wv; accp[1] += n0.y * wv;
            accp[2] += n0.z * wv; accp[3] += n0.w * wv;
            accp[4] += n1.x * wv; accp[5] += n1.y * wv;
            accp[6] += n1.z * wv; accp[7] += n1.w * wv;
            accp[8] += n8 * wv;
        }
        if (q == 1) {
#pragma unroll
            for (int i = 0; i < 9; i++) Pq[c * 9 + i] = accp[i];
        }
        __syncthreads();
        if (q == 0) {
            float* g = (c < 128) ? g_Ai : g_Bj;
            const int cc = (c < 128) ? c : (c - 128);
#pragma unroll
            for (int i = 0; i < 9; i++)
                g[(b * NPG + i) * H + cc] = accp[i] + Pq[c * 9 + i];
        }
        __threadfence();
        __syncthreads();
        if (t == 0) atomicExch(&g_abflag[b], 1u);
    } else if (bid < 64) {
        // ---- per-graph reader ----
        const int b = bid;
        const int lane = t & 31, w = t >> 5;
        float* s1r   = buf;            // 900 (pad 912)
        float* g2p   = buf + 912;      // 2000 gemm2 partials [20][100]
        float* As    = buf + 2912;     // 9*132
        float* Bs    = buf + 4100;     // 9*132
        float* Wft   = buf + 5288;     // 384 bond-major
        float* x     = buf + 5672;     // 232 used (pad 256)
        float* ss    = buf + 5928;     // 100 (pad 128)
        float* Dc    = buf + 6056;     // 128
        float* hred  = buf + 6184;     // 2 (warp sums)
        float* fp2   = buf + 6248;     // 486 (pad 512)
        float* fp    = buf + 6760;     // 243 (pad 256)
        float* Dpart = buf + 7016;     // 512
        float* Vpart = buf + 7528;     // 512
        float* red   = buf + 8040;     // 16
        float* rs2   = buf + 8056;     // 2

        // --- stage A: s1r reduce+bias+relu; Wft; readout x[0:128]; x pad zeros
        for (int idx = t; idx < O1; idx += THREADS) {
            float v = b1[idx];
#pragma unroll
            for (int c = 0; c < KS1; c++)
                v += g_s1_part[c * (BATCH * O1) + b * O1 + idx];
            s1r[idx] = fmaxf(v, 0.f);
        }
        for (int idx = t; idx < H * 3; idx += THREADS)
            Wft[(idx % 3) * H + idx / 3] = Wf[idx];
        if (t < H) {
            float sum = 0.f;
#pragma unroll
            for (int i = 0; i < NPG; i++) sum += nf[(b * NPG + i) * H + t];
            x[t] = sum;
        }
        if (t >= 228 && t < 232) x[t] = 0.f;   // pad for uniform Vpart loop
        __syncthreads();

        // --- stage B: gemm2 partials, fully unrolled for MLP
        if (t < 500) {
            const int oq = t % 25, q = t / 25;
            const int o4 = oq * 4, kb = q * 45;
            float4 acc = make_float4(0.f, 0.f, 0.f, 0.f);
#pragma unroll
            for (int kk = 0; kk < 45; kk++) {
                const int k = kb + kk;
                float4 wv = *(const float4*)(W2 + (size_t)k * O2 + o4);
                float s = s1r[k];
                acc.x += s * wv.x; acc.y += s * wv.y;
                acc.z += s * wv.z; acc.w += s * wv.w;
            }
            *(float4*)(g2p + q * O2 + o4) = acc;
        }
        __syncthreads();

        // --- stage C: ss reduce
        if (t < O2) {
            float a = b2[t];
#pragma unroll
            for (int q = 0; q < 20; q++) a += g2p[q * O2 + t];
            ss[t] = fmaxf(a, 0.f);
        }
        __syncthreads();

        // --- wait for ab writer (block b+64)
        if (t == 0) {
            while (atomicAdd(&g_abflag[b], 0u) == 0) __nanosleep(32);
            __threadfence();
        }
        __syncthreads();

        // --- stage D: x tail; As/Bs from global; D partials
        if (t < O2) x[H + t] = ss[t];
        for (int idx = t; idx < NPG * 256; idx += THREADS) {
            int i = idx >> 8, c = idx & 255;
            if (c < 128) As[i * 132 + c] = g_Ai[(b * NPG + i) * H + c];
            else         Bs[i * 132 + c - 128] = g_Bj[(b * NPG + i) * H + c - 128];
        }
        {
            const int o = t & 127, q = t >> 7;
            const int kb = q * 25;
            float d = 0.f;
#pragma unroll
            for (int kk = 0; kk < 25; kk++)
                d += ss[kb + kk] * Wa2[(size_t)(2 * H + kb + kk) * H + o];
            Dpart[q * H + o] = d;
        }
        __syncthreads();

        // --- stage E: V partials (uniform 29, fully unrolled); Dc
        {
            const int o = t & 63, q = t >> 6;
            const int kb = q * 29;
            float v = 0.f;
#pragma unroll
            for (int kk = 0; kk < 29; kk++)
                v += x[kb + kk] * Wv1[(size_t)(kb + kk) * 64 + o];
            Vpart[q * 64 + o] = v;
        }
        if (t < H)
            Dc[t] = ba2[t] + Dpart[t] + Dpart[H + t] + Dpart[2 * H + t] + Dpart[3 * H + t];
        __syncthreads();

        // --- stage F: value hidden (shuffle-reduced); pair logits
        if (t < 64) {
            float a = bv1[t];
#pragma unroll
            for (int q = 0; q < 8; q++) a += Vpart[q * 64 + t];
            float hv = fmaxf(a, 0.f) * Wv2[t];
#pragma unroll
            for (int off = 16; off; off >>= 1)
                hv += __shfl_xor_sync(0xffffffffu, hv, off);
            if ((t & 31) == 0) hred[t >> 5] = hv;
        }
        if (t < 486) {
            const int half = (t >= ASL) ? 1 : 0;
            const int pi = t - ASL * half;
            const int pair = pi / 3, bond = pi - pair * 3;
            const int i = pair / NPG, j = pair - i * NPG;
            const float4* Ap = (const float4*)(As + i * 132) + half * 16;
            const float4* Bp = (const float4*)(Bs + j * 132) + half * 16;
            const float4* Dp = (const float4*)Dc + half * 16;
            const float4* Wp = (const float4*)(Wft + bond * H) + half * 16;
            float a = 0.f;
#pragma unroll
            for (int q = 0; q < 16; q++) {
                float4 av = Ap[q], bv = Bp[q], dv = Dp[q], wv = Wp[q];
                a += fmaxf(av.x + bv.x + dv.x, 0.f) * wv.x
                   + fmaxf(av.y + bv.y + dv.y, 0.f) * wv.y
                   + fmaxf(av.z + bv.z + dv.z, 0.f) * wv.z
                   + fmaxf(av.w + bv.w + dv.w, 0.f) * wv.w;
            }
            fp2[t] = a;
        }
        __syncthreads();
        if (t < ASL) fp[t] = fp2[t] + fp2[ASL + t] + bf[t % 3];
        __syncthreads();

        // --- gather + softmax + value out
        float g = -INFINITY;
        if (t < ASL) g = fp[imask[b * ASL + t]] + mask[b * ASL + t];
        float v = g;
#pragma unroll
        for (int off = 16; off; off >>= 1) v = fmaxf(v, __shfl_xor_sync(0xffffffffu, v, off));
        if (lane == 0) red[w] = v;
        __syncthreads();
        if (t == 0) {
            float m = red[0];
#pragma unroll
            for (int i = 1; i < 16; i++) m = fmaxf(m, red[i]);
            rs2[0] = m;
        }
        __syncthreads();
        float e = (t < ASL) ? __expf(g - rs2[0]) : 0.f;
        v = e;
#pragma unroll
        for (int off = 16; off; off >>= 1) v += __shfl_xor_sync(0xffffffffu, v, off);
        if (lane == 0) red[w] = v;
        __syncthreads();
        if (t == 0) {
            float s = 0.f;
#pragma unroll
            for (int i = 0; i < 16; i++) s += red[i];
            rs2[1] = s;
            out[BATCH * ASL + b] = bv2[0] + hred[0] + hred[1];
        }
        __syncthreads();
        if (t < ASL) out[b * ASL + t] = e / rs2[1];
    }
}

extern "C" void kernel_launch(void* const* d_in, const int* in_sizes, int n_in,
                              void* d_out, int out_size) {
    const float* nf   = (const float*)d_in[0];
    const float* spec = (const float*)d_in[1];
    const float* mask = (const float*)d_in[3];
    const int*   imask= (const int*)  d_in[4];
    const float* W1   = (const float*)d_in[5];
    const float* b1   = (const float*)d_in[6];
    const float* W2   = (const float*)d_in[7];
    const float* b2   = (const float*)d_in[8];
    const float* Wv1  = (const float*)d_in[9];
    const float* bv1  = (const float*)d_in[10];
    const float* Wv2  = (const float*)d_in[11];
    const float* bv2  = (const float*)d_in[12];
    const float* Wa2  = (const float*)d_in[13];
    const float* ba2  = (const float*)d_in[14];
    const float* Wf   = (const float*)d_in[15];
    const float* bf   = (const float*)d_in[16];
    float* out = (float*)d_out;

    fused_kernel<<<NB, THREADS>>>(nf, spec, mask, imask, W1, b1, W2, b2,
                                  Wv1, bv1, Wv2, bv2, Wa2, ba2, Wf, bf, out);
}

// round 16
// speedup vs baseline: 1.2105x; 1.0548x over previous
#include <cuda_runtime.h>
#include <math.h>
#include <stdint.h>

#define NB 148
#define THREADS 512
#define BATCH 64
#define NPG 9
#define NTOT (BATCH*NPG)   // 576
#define H 128
#define K1 1801
#define O1 900
#define O2 100
#define ASL 243
#define NT1 15             // 15 n-tiles x 64 outs
#define KS1 9
#define KC1 201            // 9*201 = 1809 >= 1801

// scratch (no allocation allowed)
__device__ float g_s1_part[KS1 * BATCH * O1];
__device__ float g_Ai[NTOT * H];
__device__ float g_Bj[NTOT * H];
__device__ unsigned g_abflag[BATCH];
__device__ unsigned g_count = 0;
__device__ unsigned g_gen = 0;

__device__ __forceinline__ void grid_barrier() {
    __syncthreads();
    __threadfence();
    if (threadIdx.x == 0) {
        unsigned gen = *(volatile unsigned*)&g_gen;
        if (atomicAdd(&g_count, 1u) == NB - 1) {
            g_count = 0;
            __threadfence();
            atomicAdd(&g_gen, 1u);
        } else {
            while (*(volatile unsigned*)&g_gen == gen) __nanosleep(32);
        }
    }
    __syncthreads();
}

__device__ __forceinline__ uint32_t tf32_hi_bits(float x) {
    uint32_t r;
    asm("cvt.rna.tf32.f32 %0, %1;" : "=r"(r) : "f"(x));
    return r;
}

__device__ __forceinline__ void mma_tf32(float* d, const uint32_t* a,
                                         uint32_t b0, uint32_t b1) {
    asm volatile(
        "mma.sync.aligned.m16n8k8.row.col.f32.tf32.tf32.f32 "
        "{%0,%1,%2,%3}, {%4,%5,%6,%7}, {%8,%9}, {%0,%1,%2,%3};"
        : "+f"(d[0]), "+f"(d[1]), "+f"(d[2]), "+f"(d[3])
        : "r"(a[0]), "r"(a[1]), "r"(a[2]), "r"(a[3]), "r"(b0), "r"(b1));
}

__global__ __launch_bounds__(THREADS, 1)
void fused_kernel(const float* __restrict__ nf, const float* __restrict__ spec,
                  const float* __restrict__ mask, const int* __restrict__ imask,
                  const float* __restrict__ W1, const float* __restrict__ b1,
                  const float* __restrict__ W2, const float* __restrict__ b2,
                  const float* __restrict__ Wv1, const float* __restrict__ bv1,
                  const float* __restrict__ Wv2, const float* __restrict__ bv2,
                  const float* __restrict__ Wa2, const float* __restrict__ ba2,
                  const float* __restrict__ Wf, const float* __restrict__ bf,
                  float* __restrict__ out) {
    __shared__ __align__(16) float buf[12288];   // 48KB, reused per phase
    const int t = threadIdx.x;
    const int bid = blockIdx.x;

    // reset per-graph ab flags (ordered before release by grid_barrier's fence)
    if (bid < BATCH && t == 0) g_abflag[bid] = 0;

    // ===== Phase 1: gemm1 via 3xTF32 mma (135 blocks; R13 two-sync staging) =====
    if (bid < NT1 * KS1) {
        const int nt = bid / KS1, ks = bid % KS1;
        const int kbeg = ks * KC1;
        const int kend = min(kbeg + KC1, K1);
        const int nch = (kend - kbeg + 31) >> 5;

        float* A_hi = buf;             // [64][36]
        float* A_lo = buf + 2304;      // [64][36]
        float* B_hi = buf + 4608;      // [32][68]
        float* B_lo = buf + 6784;      // [32][68]

        const int lane = t & 31, w = t >> 5;
        const int g = lane >> 2, tig = lane & 3;
        const int m0 = (w & 3) * 16;          // batch tile base
        const int ng = (w >> 2) * 16;         // local out base (two n8 tiles)

        // staging coords
        const int a_row = t >> 5;             // + 16j
        const int a_kk  = t & 31;
        const int b_k   = t >> 6;             // + 8j
        const int b_o   = t & 63;
        const bool b_ook = (nt * 64 + b_o) < O1;
        const float* wsrc = W1 + nt * 64 + b_o;

        float pa[4], pb[4];
        {   // prefetch chunk 0
            const int k0g = kbeg;
#pragma unroll
            for (int j = 0; j < 4; j++) {
                int kg = k0g + a_kk;
                pa[j] = (kg < kend) ? spec[(a_row + 16 * j) * K1 + kg] : 0.f;
            }
#pragma unroll
            for (int j = 0; j < 4; j++) {
                int kg = k0g + b_k + 8 * j;
                pb[j] = (kg < kend && b_ook) ? wsrc[(size_t)kg * O1] : 0.f;
            }
        }

        float d0[4] = {0.f, 0.f, 0.f, 0.f};
        float d1[4] = {0.f, 0.f, 0.f, 0.f};

        for (int c = 0; c < nch; c++) {
            __syncthreads();
            // split + store staged regs
#pragma unroll
            for (int j = 0; j < 4; j++) {
                uint32_t hb = tf32_hi_bits(pa[j]);
                float hv = __uint_as_float(hb);
                A_hi[(a_row + 16 * j) * 36 + a_kk] = hv;
                A_lo[(a_row + 16 * j) * 36 + a_kk] = pa[j] - hv;
            }
#pragma unroll
            for (int j = 0; j < 4; j++) {
                uint32_t hb = tf32_hi_bits(pb[j]);
                float hv = __uint_as_float(hb);
                B_hi[(b_k + 8 * j) * 68 + b_o] = hv;
                B_lo[(b_k + 8 * j) * 68 + b_o] = pb[j] - hv;
            }
            __syncthreads();
            if (c + 1 < nch) {   // prefetch next chunk during compute
                const int k0g = kbeg + (c + 1) * 32;
#pragma unroll
                for (int j = 0; j < 4; j++) {
                    int kg = k0g + a_kk;
                    pa[j] = (kg < kend) ? spec[(a_row + 16 * j) * K1 + kg] : 0.f;
                }
#pragma unroll
                for (int j = 0; j < 4; j++) {
                    int kg = k0g + b_k + 8 * j;
                    pb[j] = (kg < kend && b_ook) ? wsrc[(size_t)kg * O1] : 0.f;
                }
            }
            // 4 k8-steps of 3xTF32 mma
#pragma unroll
            for (int s = 0; s < 4; s++) {
                const int k0 = s * 8;
                const float* Ah0 = A_hi + (m0 + g) * 36 + k0 + tig;
                const float* Ah8 = A_hi + (m0 + g + 8) * 36 + k0 + tig;
                const float* Al0 = A_lo + (m0 + g) * 36 + k0 + tig;
                const float* Al8 = A_lo + (m0 + g + 8) * 36 + k0 + tig;
                uint32_t ah[4], al[4];
                ah[0] = __float_as_uint(Ah0[0]);
                ah[1] = __float_as_uint(Ah8[0]);
                ah[2] = __float_as_uint(Ah0[4]);
                ah[3] = __float_as_uint(Ah8[4]);
                al[0] = __float_as_uint(Al0[0]);
                al[1] = __float_as_uint(Al8[0]);
                al[2] = __float_as_uint(Al0[4]);
                al[3] = __float_as_uint(Al8[4]);
                const int kr0 = (k0 + tig) * 68, kr1 = (k0 + tig + 4) * 68;
                // tile 0: outs ng..ng+7
                {
                    uint32_t bh0 = __float_as_uint(B_hi[kr0 + ng + g]);
                    uint32_t bh1 = __float_as_uint(B_hi[kr1 + ng + g]);
                    uint32_t bl0 = __float_as_uint(B_lo[kr0 + ng + g]);
                    uint32_t bl1 = __float_as_uint(B_lo[kr1 + ng + g]);
                    mma_tf32(d0, ah, bh0, bh1);
                    mma_tf32(d0, al, bh0, bh1);
                    mma_tf32(d0, ah, bl0, bl1);
                }
                // tile 1: outs ng+8..ng+15
                {
                    uint32_t bh0 = __float_as_uint(B_hi[kr0 + ng + 8 + g]);
                    uint32_t bh1 = __float_as_uint(B_hi[kr1 + ng + 8 + g]);
                    uint32_t bl0 = __float_as_uint(B_lo[kr0 + ng + 8 + g]);
                    uint32_t bl1 = __float_as_uint(B_lo[kr1 + ng + 8 + g]);
                    mma_tf32(d1, ah, bh0, bh1);
                    mma_tf32(d1, al, bh0, bh1);
                    mma_tf32(d1, ah, bl0, bl1);
                }
            }
        }
        // epilogue: c0=(g,2tig), c1=(g,2tig+1), c2=(g+8,2tig), c3=(g+8,2tig+1)
        float* dst = g_s1_part + ks * (BATCH * O1);
#pragma unroll
        for (int tile = 0; tile < 2; tile++) {
            const float* d = tile ? d1 : d0;
            const int o0g = nt * 64 + ng + tile * 8 + 2 * tig;
            const int r0 = m0 + g, r8 = m0 + g + 8;
            if (o0g < O1) {
                dst[r0 * O1 + o0g] = d[0];
                dst[r8 * O1 + o0g] = d[2];
            }
            if (o0g + 1 < O1) {
                dst[r0 * O1 + o0g + 1] = d[1];
                dst[r8 * O1 + o0g + 1] = d[3];
            }
        }
    }

    grid_barrier();

    // ===== Phase 2 (byte-identical to R13) =====
    if (bid >= 64 && bid < 128) {
        // ---- ab writer for graph b = bid-64 ----
        const int b = bid - 64;
        float* nfs_t = buf;           // [128][12] transposed relu(nf)
        float* Pq    = buf + 1536;    // 2304 partials for q=1
        for (int idx = t; idx < NPG * H; idx += THREADS) {
            int i = idx >> 7, k = idx & 127;
            nfs_t[k * 12 + i] = fmaxf(nf[(b * NPG + i) * H + k], 0.f);
        }
        __syncthreads();
        const int c = t & 255, q = t >> 8;
        const int kb = q * 64;
        const float* wbase = Wa2 + ((c < 128) ? c : (H * H + (c - 128)));
        float accp[9];
#pragma unroll
        for (int i = 0; i < 9; i++) accp[i] = 0.f;
#pragma unroll 4
        for (int k = 0; k < 64; k++) {
            const int kg = kb + k;
            float wv = wbase[(size_t)kg * H];
            const float* nr = nfs_t + kg * 12;
            float4 n0 = *(const float4*)nr;
            float4 n1 = *(const float4*)(nr + 4);
            float n8 = nr[8];
            accp[0] += n0.x * wv; accp[1] += n0.y * wv;
            accp[2] += n0.z * wv; accp[3] += n0.w * wv;
            accp[4] += n1.x * wv; accp[5] += n1.y * wv;
            accp[6] += n1.z * wv; accp[7] += n1.w * wv;
            accp[8] += n8 * wv;
        }
        if (q == 1) {
#pragma unroll
            for (int i = 0; i < 9; i++) Pq[c * 9 + i] = accp[i];
        }
        __syncthreads();
        if (q == 0) {
            float* g2 = (c < 128) ? g_Ai : g_Bj;
            const int cc = (c < 128) ? c : (c - 128);
#pragma unroll
            for (int i = 0; i < 9; i++)
                g2[(b * NPG + i) * H + cc] = accp[i] + Pq[c * 9 + i];
        }
        __threadfence();
        __syncthreads();
        if (t == 0) atomicExch(&g_abflag[b], 1u);
    } else if (bid < 64) {
        // ---- per-graph reader ----
        const int b = bid;
        const int lane = t & 31, w = t >> 5;
        float* s1r   = buf;            // 900 (pad 912)
        float* g2p   = buf + 912;      // 2000 gemm2 partials [20][100]
        float* As    = buf + 2912;     // 9*132
        float* Bs    = buf + 4100;     // 9*132
        float* Wft   = buf + 5288;     // 384 bond-major
        float* x     = buf + 5672;     // 232 used (pad 256)
        float* ss    = buf + 5928;     // 100 (pad 128)
        float* Dc    = buf + 6056;     // 128
        float* hred  = buf + 6184;     // 2 (warp sums)
        float* fp2   = buf + 6248;     // 486 (pad 512)
        float* fp    = buf + 6760;     // 243 (pad 256)
        float* Dpart = buf + 7016;     // 512
        float* Vpart = buf + 7528;     // 512
        float* red   = buf + 8040;     // 16
        float* rs2   = buf + 8056;     // 2

        // --- stage A: s1r reduce+bias+relu; Wft; readout x[0:128]; x pad zeros
        for (int idx = t; idx < O1; idx += THREADS) {
            float v = b1[idx];
#pragma unroll
            for (int c = 0; c < KS1; c++)
                v += g_s1_part[c * (BATCH * O1) + b * O1 + idx];
            s1r[idx] = fmaxf(v, 0.f);
        }
        for (int idx = t; idx < H * 3; idx += THREADS)
            Wft[(idx % 3) * H + idx / 3] = Wf[idx];
        if (t < H) {
            float sum = 0.f;
#pragma unroll
            for (int i = 0; i < NPG; i++) sum += nf[(b * NPG + i) * H + t];
            x[t] = sum;
        }
        if (t >= 228 && t < 232) x[t] = 0.f;   // pad for uniform Vpart loop
        __syncthreads();

        // --- stage B: gemm2 partials, fully unrolled for MLP
        if (t < 500) {
            const int oq = t % 25, q = t / 25;
            const int o4 = oq * 4, kb = q * 45;
            float4 acc = make_float4(0.f, 0.f, 0.f, 0.f);
#pragma unroll
            for (int kk = 0; kk < 45; kk++) {
                const int k = kb + kk;
                float4 wv = *(const float4*)(W2 + (size_t)k * O2 + o4);
                float s = s1r[k];
                acc.x += s * wv.x; acc.y += s * wv.y;
                acc.z += s * wv.z; acc.w += s * wv.w;
            }
            *(float4*)(g2p + q * O2 + o4) = acc;
        }
        __syncthreads();

        // --- stage C: ss reduce
        if (t < O2) {
            float a = b2[t];
#pragma unroll
            for (int q = 0; q < 20; q++) a += g2p[q * O2 + t];
            ss[t] = fmaxf(a, 0.f);
        }
        __syncthreads();

        // --- wait for ab writer (block b+64)
        if (t == 0) {
            while (atomicAdd(&g_abflag[b], 0u) == 0) __nanosleep(32);
            __threadfence();
        }
        __syncthreads();

        // --- stage D: x tail; As/Bs from global; D partials
        if (t < O2) x[H + t] = ss[t];
        for (int idx = t; idx < NPG * 256; idx += THREADS) {
            int i = idx >> 8, c = idx & 255;
            if (c < 128) As[i * 132 + c] = g_Ai[(b * NPG + i) * H + c];
            else         Bs[i * 132 + c - 128] = g_Bj[(b * NPG + i) * H + c - 128];
        }
        {
            const int o = t & 127, q = t >> 7;
            const int kb = q * 25;
            float d = 0.f;
#pragma unroll
            for (int kk = 0; kk < 25; kk++)
                d += ss[kb + kk] * Wa2[(size_t)(2 * H + kb + kk) * H + o];
            Dpart[q * H + o] = d;
        }
        __syncthreads();

        // --- stage E: V partials (uniform 29, fully unrolled); Dc
        {
            const int o = t & 63, q = t >> 6;
            const int kb = q * 29;
            float v = 0.f;
#pragma unroll
            for (int kk = 0; kk < 29; kk++)
                v += x[kb + kk] * Wv1[(size_t)(kb + kk) * 64 + o];
            Vpart[q * 64 + o] = v;
        }
        if (t < H)
            Dc[t] = ba2[t] + Dpart[t] + Dpart[H + t] + Dpart[2 * H + t] + Dpart[3 * H + t];
        __syncthreads();

        // --- stage F: value hidden (shuffle-reduced); pair logits
        if (t < 64) {
            float a = bv1[t];
#pragma unroll
            for (int q = 0; q < 8; q++) a += Vpart[q * 64 + t];
            float hv = fmaxf(a, 0.f) * Wv2[t];
#pragma unroll
            for (int off = 16; off; off >>= 1)
                hv += __shfl_xor_sync(0xffffffffu, hv, off);
            if ((t & 31) == 0) hred[t >> 5] = hv;
        }
        if (t < 486) {
            const int half = (t >= ASL) ? 1 : 0;
            const int pi = t - ASL * half;
            const int pair = pi / 3, bond = pi - pair * 3;
            const int i = pair / NPG, j = pair - i * NPG;
            const float4* Ap = (const float4*)(As + i * 132) + half * 16;
            const float4* Bp = (const float4*)(Bs + j * 132) + half * 16;
            const float4* Dp = (const float4*)Dc + half * 16;
            const float4* Wp = (const float4*)(Wft + bond * H) + half * 16;
            float a = 0.f;
#pragma unroll
            for (int q = 0; q < 16; q++) {
                float4 av = Ap[q], bv = Bp[q], dv = Dp[q], wv = Wp[q];
                a += fmaxf(av.x + bv.x + dv.x, 0.f) * wv.x
                   + fmaxf(av.y + bv.y + dv.y, 0.f) * wv.y
                   + fmaxf(av.z + bv.z + dv.z, 0.f) * wv.z
                   + fmaxf(av.w + bv.w + dv.w, 0.f) * wv.w;
            }
            fp2[t] = a;
        }
        __syncthreads();
        if (t < ASL) fp[t] = fp2[t] + fp2[ASL + t] + bf[t % 3];
        __syncthreads();

        // --- gather + softmax + value out
        float g = -INFINITY;
        if (t < ASL) g = fp[imask[b * ASL + t]] + mask[b * ASL + t];
        float v = g;
#pragma unroll
        for (int off = 16; off; off >>= 1) v = fmaxf(v, __shfl_xor_sync(0xffffffffu, v, off));
        if (lane == 0) red[w] = v;
        __syncthreads();
        if (t == 0) {
            float m = red[0];
#pragma unroll
            for (int i = 1; i < 16; i++) m = fmaxf(m, red[i]);
            rs2[0] = m;
        }
        __syncthreads();
        float e = (t < ASL) ? __expf(g - rs2[0]) : 0.f;
        v = e;
#pragma unroll
        for (int off = 16; off; off >>= 1) v += __shfl_xor_sync(0xffffffffu, v, off);
        if (lane == 0) red[w] = v;
        __syncthreads();
        if (t == 0) {
            float s = 0.f;
#pragma unroll
            for (int i = 0; i < 16; i++) s += red[i];
            rs2[1] = s;
            out[BATCH * ASL + b] = bv2[0] + hred[0] + hred[1];
        }
        __syncthreads();
        if (t < ASL) out[b * ASL + t] = e / rs2[1];
    }
}

extern "C" void kernel_launch(void* const* d_in, const int* in_sizes, int n_in,
                              void* d_out, int out_size) {
    const float* nf   = (const float*)d_in[0];
    const float* spec = (const float*)d_in[1];
    const float* mask = (const float*)d_in[3];
    const int*   imask= (const int*)  d_in[4];
    const float* W1   = (const float*)d_in[5];
    const float* b1   = (const float*)d_in[6];
    const float* W2   = (const float*)d_in[7];
    const float* b2   = (const float*)d_in[8];
    const float* Wv1  = (const float*)d_in[9];
    const float* bv1  = (const float*)d_in[10];
    const float* Wv2  = (const float*)d_in[11];
    const float* bv2  = (const float*)d_in[12];
    const float* Wa2  = (const float*)d_in[13];
    const float* ba2  = (const float*)d_in[14];
    const float* Wf   = (const float*)d_in[15];
    const float* bf   = (const float*)d_in[16];
    float* out = (float*)d_out;

    fused_kernel<<<NB, THREADS>>>(nf, spec, mask, imask, W1, b1, W2, b2,
                                  Wv1, bv1, Wv2, bv2, Wa2, ba2, Wf, bf, out);
}